// round 8
// baseline (speedup 1.0000x reference)
#include <cuda_runtime.h>
#include <cstdint>

// ---------------------------------------------------------------------------
// HexagonalSensor: 16.7M photons -> hex-pixel scatter add (1801 bins)
// R8: pure REDG privatized scatter (hybrid reverted); ANALYTIC pixel index
// (no LUT, no LDS — hexagon row-prefix quadratic); d_out zero fused into hex;
// 4-warps-per-pixel reduce with REDG combine. 2 launches.
// ---------------------------------------------------------------------------

#define NCTA 592          // 4 CTAs per SM
#define TPB  256
#define MAX_PIX 2048

// scratch[pix * NCTA + cta]  (pix-major so reduce reads contiguous float4s)
__device__ float g_scratch[MAX_PIX * NCTA];

// ------------------------- per-photon pipeline -----------------------------
__device__ __forceinline__ void photon_one(
    float x, float y, float v,
    float ca, float sa, float ox, float oy,
    float c1, float c2, float c3,
    int R, int twoR, int twoRp3, int fourRp3, int off0R,
    float* __restrict__ my_col)
{
    // rotate into grid frame
    float xs = x - ox;
    float ys = y - oy;
    float xrot = fmaf(ca, xs, -(sa * ys));
    float yrot = fmaf(sa, xs, ca * ys);

    // cartesian -> axial (constants folded with 1/hex_size)
    float q = fmaf(c1, xrot, c2 * yrot);
    float r = c3 * yrot;
    float s = -q - r;

    // round-half-even via magic add; integer falls out of mantissa bits
    const float MAG = 12582912.0f;           // 1.5 * 2^23
    const int   MAGBITS = 0x4B400000;
    float fq = q + MAG, fr = r + MAG, fs = s + MAG;
    float qr = fq - MAG, rr = fr - MAG, sr = fs - MAG;
    int qi = __float_as_int(fq) - MAGBITS;
    int ri = __float_as_int(fr) - MAGBITS;
    int si = __float_as_int(fs) - MAGBITS;

    // cube-round fixup (faithful to reference _axial_round)
    float qd = fabsf(qr - q), rd = fabsf(rr - r), sd = fabsf(sr - s);
    bool cq = (qd > rd) && (qd > sd);
    bool cr = (rd > qd) && (rd > sd);
    if (cq)      qi = -ri - si;
    else if (cr) ri = -qi - si;

    // ---- analytic hex pixel id (replaces LUT + LDS) ----
    // rows enumerated q = -R..R, r ascending within row.
    // q<=0: pix = t*(t+2R+3)/2 + r          (t = q+R)
    // q> 0: pix = q*(4R+3-q)/2 + off0R + r  (off0R = R(R+1)+R(R-1)/2+R)
    int t = qi + R;
    int u = ri + R;
    int w = qi + ri + R;
    bool valid = ((unsigned)t <= (unsigned)twoR) &
                 ((unsigned)u <= (unsigned)twoR) &
                 ((unsigned)w <= (unsigned)twoR);
    int pixneg = ((t  * (t + twoRp3))  >> 1) + ri;
    int pixpos = ((qi * (fourRp3 - qi)) >> 1) + off0R + ri;
    int pix = (qi <= 0) ? pixneg : pixpos;

    if (valid)
        atomicAdd(my_col + (unsigned)pix * NCTA, v);   // RED.E.ADD.F32
}

__global__ __launch_bounds__(TPB)
void hex_kernel(const float* __restrict__ x,
                const float* __restrict__ y,
                const float* __restrict__ vals,
                const float* __restrict__ p_hs,
                const float* __restrict__ p_rot,
                const float* __restrict__ p_ox,
                const float* __restrict__ p_oy,
                const int* __restrict__ p_qmin,
                int n4, int npix,
                float* __restrict__ out)
{
    float* my_col = g_scratch + blockIdx.x;   // per-CTA private global column

    // fused zero: this CTA's scratch column (+ CTA 0 zeroes d_out for reduce)
    for (int p = threadIdx.x; p < npix; p += TPB)
        my_col[(unsigned)p * NCTA] = 0.0f;
    if (blockIdx.x == 0)
        for (int p = threadIdx.x; p < npix; p += TPB)
            out[p] = 0.0f;

    float hs  = *p_hs;
    float rot = *p_rot;
    float ox  = *p_ox;
    float oy  = *p_oy;
    int qmin  = *p_qmin;

    float ca = cosf(-rot), sa = sinf(-rot);
    float inv_hs = 1.0f / hs;
    float c1 = 0.57735026919f * inv_hs;          // (sqrt3/3)/hs
    float c2 = -0.33333333333f * inv_hs;         // -(1/3)/hs
    float c3 = 0.66666666667f * inv_hs;          // (2/3)/hs

    int R       = -qmin;                         // 24 for this layout
    int twoR    = 2 * R;
    int twoRp3  = 2 * R + 3;
    int fourRp3 = 4 * R + 3;
    int off0R   = R * (R + 1) + ((R * (R - 1)) >> 1) + R;

    __syncthreads();   // membar.cta: column zeros ordered before our REDs

    const float4* x4 = reinterpret_cast<const float4*>(x);
    const float4* y4 = reinterpret_cast<const float4*>(y);
    const float4* v4 = reinterpret_cast<const float4*>(vals);

    int stride = gridDim.x * blockDim.x;
    for (int i = blockIdx.x * blockDim.x + threadIdx.x; i < n4; i += stride) {
        float4 xx = x4[i];
        float4 yy = y4[i];
        float4 vv = v4[i];
        photon_one(xx.x, yy.x, vv.x, ca, sa, ox, oy, c1, c2, c3,
                   R, twoR, twoRp3, fourRp3, off0R, my_col);
        photon_one(xx.y, yy.y, vv.y, ca, sa, ox, oy, c1, c2, c3,
                   R, twoR, twoRp3, fourRp3, off0R, my_col);
        photon_one(xx.z, yy.z, vv.z, ca, sa, ox, oy, c1, c2, c3,
                   R, twoR, twoRp3, fourRp3, off0R, my_col);
        photon_one(xx.w, yy.w, vv.w, ca, sa, ox, oy, c1, c2, c3,
                   R, twoR, twoRp3, fourRp3, off0R, my_col);
    }
}

// ---------------- reduce: 4 warps per pixel, REDG combine ------------------
// NCTA/4 = 148 float4 per pixel row = 4 warps x 37 float4.
__global__ __launch_bounds__(256)
void reduce_kernel(float* __restrict__ out, int npix) {
    int task = (blockIdx.x * blockDim.x + threadIdx.x) >> 5;
    int lane = threadIdx.x & 31;
    if (task >= npix * 4) return;
    int pix = task >> 2;
    int w   = task & 3;

    const float4* row = reinterpret_cast<const float4*>(
        g_scratch + (size_t)pix * NCTA) + w * 37;

    float s0 = 0.f, s1 = 0.f, s2 = 0.f, s3 = 0.f;
    for (int j = lane; j < 37; j += 32) {        // lanes 0..4 do 2, rest 1
        float4 t = row[j];
        s0 += t.x; s1 += t.y; s2 += t.z; s3 += t.w;
    }
    float s = (s0 + s1) + (s2 + s3);
    #pragma unroll
    for (int off = 16; off > 0; off >>= 1)
        s += __shfl_down_sync(0xFFFFFFFFu, s, off);
    if (lane == 0)
        atomicAdd(out + pix, s);                 // out pre-zeroed by hex CTA 0
}

// ------------------------------ launch -------------------------------------
extern "C" void kernel_launch(void* const* d_in, const int* in_sizes, int n_in,
                              void* d_out, int out_size)
{
    const float* x    = (const float*)d_in[0];
    const float* y    = (const float*)d_in[1];
    const float* vals = (const float*)d_in[2];
    const float* hs   = (const float*)d_in[4];
    const float* rot  = (const float*)d_in[5];
    const float* ox   = (const float*)d_in[6];
    const float* oy   = (const float*)d_in[7];
    const int*   qmin = (const int*)  d_in[8];

    int n = in_sizes[0];
    int npix = out_size;                 // 1801
    if (npix > MAX_PIX) npix = MAX_PIX;

    hex_kernel<<<NCTA, TPB>>>(x, y, vals, hs, rot, ox, oy, qmin,
                              n / 4, npix, (float*)d_out);
    int nwarps = npix * 4;
    int nblk = (nwarps * 32 + 255) / 256;
    reduce_kernel<<<nblk, 256>>>((float*)d_out, npix);
}

// round 14
// speedup vs baseline: 1.1017x; 1.1017x over previous
#include <cuda_runtime.h>
#include <cstdint>

// ---------------------------------------------------------------------------
// HexagonalSensor: 16.7M photons -> hex-pixel scatter add (1801 bins)
// R11 (= R9 resubmit after infra failure): cta-major scratch transpose —
// each CTA's histogram is one contiguous 7.2KB region so a warp's 32 random
// REDG addresses fall in ~25 sectors (sector coalescing) instead of 32
// distinct far-apart sectors. __ldcs streaming inputs keep scratch
// L2-resident. Coalesced transposed reduce. 2 launches.
// ---------------------------------------------------------------------------

#define NCTA   592        // 4 CTAs per SM
#define TPB    256
#define PADPIX 1808       // 1801 padded to /16; per-CTA row = 7232 B

// scratch[cta * PADPIX + pix]  (cta-major: warp atomic footprint = 7.2 KB)
__device__ float g_scratch[NCTA * PADPIX];

// ------------------------- per-photon pipeline -----------------------------
__device__ __forceinline__ void photon_one(
    float x, float y, float v,
    float ca, float sa, float ox, float oy,
    float c1, float c2, float c3,
    int R, int twoR, int twoRp3, int fourRp3, int off0R,
    float* __restrict__ my_hist)
{
    // rotate into grid frame
    float xs = x - ox;
    float ys = y - oy;
    float xrot = fmaf(ca, xs, -(sa * ys));
    float yrot = fmaf(sa, xs, ca * ys);

    // cartesian -> axial (constants folded with 1/hex_size)
    float q = fmaf(c1, xrot, c2 * yrot);
    float r = c3 * yrot;
    float s = -q - r;

    // round-half-even via magic add; integer falls out of mantissa bits
    const float MAG = 12582912.0f;           // 1.5 * 2^23
    const int   MAGBITS = 0x4B400000;
    float fq = q + MAG, fr = r + MAG, fs = s + MAG;
    float qr = fq - MAG, rr = fr - MAG, sr = fs - MAG;
    int qi = __float_as_int(fq) - MAGBITS;
    int ri = __float_as_int(fr) - MAGBITS;
    int si = __float_as_int(fs) - MAGBITS;

    // cube-round fixup (faithful to reference _axial_round)
    float qd = fabsf(qr - q), rd = fabsf(rr - r), sd = fabsf(sr - s);
    bool cq = (qd > rd) && (qd > sd);
    bool cr = (rd > qd) && (rd > sd);
    if (cq)      qi = -ri - si;
    else if (cr) ri = -qi - si;

    // analytic hex pixel id (rows q=-R..R, r ascending; verified R7/R8)
    int t = qi + R;
    int u = ri + R;
    int w = qi + ri + R;
    bool valid = ((unsigned)t <= (unsigned)twoR) &
                 ((unsigned)u <= (unsigned)twoR) &
                 ((unsigned)w <= (unsigned)twoR);
    int pixneg = ((t  * (t + twoRp3))  >> 1) + ri;
    int pixpos = ((qi * (fourRp3 - qi)) >> 1) + off0R + ri;
    int pix = (qi <= 0) ? pixneg : pixpos;

    if (valid)
        atomicAdd(my_hist + pix, v);          // RED.E.ADD.F32, 7.2KB footprint
}

__global__ __launch_bounds__(TPB)
void hex_kernel(const float* __restrict__ x,
                const float* __restrict__ y,
                const float* __restrict__ vals,
                const float* __restrict__ p_hs,
                const float* __restrict__ p_rot,
                const float* __restrict__ p_ox,
                const float* __restrict__ p_oy,
                const int* __restrict__ p_qmin,
                int n4, int npix,
                float* __restrict__ out)
{
    float* my_hist = g_scratch + blockIdx.x * PADPIX;  // contiguous 7.2 KB

    // fused zero: contiguous coalesced float4 sweep of this CTA's row
    float4* h4 = reinterpret_cast<float4*>(my_hist);
    float4 z = make_float4(0.f, 0.f, 0.f, 0.f);
    for (int p = threadIdx.x; p < PADPIX / 4; p += TPB)
        h4[p] = z;
    if (blockIdx.x == 0)
        for (int p = threadIdx.x; p < npix; p += TPB)
            out[p] = 0.0f;                     // reduce REDs into this

    float hs  = *p_hs;
    float rot = *p_rot;
    float ox  = *p_ox;
    float oy  = *p_oy;
    int qmin  = *p_qmin;

    float ca = cosf(-rot), sa = sinf(-rot);
    float inv_hs = 1.0f / hs;
    float c1 = 0.57735026919f * inv_hs;          // (sqrt3/3)/hs
    float c2 = -0.33333333333f * inv_hs;         // -(1/3)/hs
    float c3 = 0.66666666667f * inv_hs;          // (2/3)/hs

    int R       = -qmin;                         // 24
    int twoR    = 2 * R;
    int twoRp3  = 2 * R + 3;
    int fourRp3 = 4 * R + 3;
    int off0R   = R * (R + 1) + ((R * (R - 1)) >> 1) + R;

    __syncthreads();   // CTA-scope: zeros visible before any RED from this CTA

    const float4* x4 = reinterpret_cast<const float4*>(x);
    const float4* y4 = reinterpret_cast<const float4*>(y);
    const float4* v4 = reinterpret_cast<const float4*>(vals);

    int stride = gridDim.x * blockDim.x;
    for (int i = blockIdx.x * blockDim.x + threadIdx.x; i < n4; i += stride) {
        float4 xx = __ldcs(&x4[i]);     // evict-first: keep scratch resident
        float4 yy = __ldcs(&y4[i]);
        float4 vv = __ldcs(&v4[i]);
        photon_one(xx.x, yy.x, vv.x, ca, sa, ox, oy, c1, c2, c3,
                   R, twoR, twoRp3, fourRp3, off0R, my_hist);
        photon_one(xx.y, yy.y, vv.y, ca, sa, ox, oy, c1, c2, c3,
                   R, twoR, twoRp3, fourRp3, off0R, my_hist);
        photon_one(xx.z, yy.z, vv.z, ca, sa, ox, oy, c1, c2, c3,
                   R, twoR, twoRp3, fourRp3, off0R, my_hist);
        photon_one(xx.w, yy.w, vv.w, ca, sa, ox, oy, c1, c2, c3,
                   R, twoR, twoRp3, fourRp3, off0R, my_hist);
    }
}

// ----------- reduce (transposed): thread-per-pixel x 4 cta-groups ----------
// blockIdx.x = group*8 + pixel_block. Thread sums 148 CTAs' slots for its
// pixel (coalesced across the warp at every step), REDs once into out.
#define CTA_GROUPS 4
#define PIX_BLOCKS 8          // 8 * 256 = 2048 >= 1801

__global__ __launch_bounds__(256)
void reduce_kernel(float* __restrict__ out, int npix) {
    int pb  = blockIdx.x & (PIX_BLOCKS - 1);
    int g   = blockIdx.x >> 3;
    int pix = pb * 256 + threadIdx.x;
    if (pix >= npix) return;

    const float* base = g_scratch + (size_t)g * (NCTA / CTA_GROUPS) * PADPIX + pix;
    float s0 = 0.f, s1 = 0.f, s2 = 0.f, s3 = 0.f;
    #pragma unroll
    for (int c = 0; c < NCTA / CTA_GROUPS; c += 4) {   // 148 rows, MLP=4
        s0 += base[(c + 0) * PADPIX];
        s1 += base[(c + 1) * PADPIX];
        s2 += base[(c + 2) * PADPIX];
        s3 += base[(c + 3) * PADPIX];
    }
    atomicAdd(out + pix, (s0 + s1) + (s2 + s3));   // out pre-zeroed by hex
}

// ------------------------------ launch -------------------------------------
extern "C" void kernel_launch(void* const* d_in, const int* in_sizes, int n_in,
                              void* d_out, int out_size)
{
    const float* x    = (const float*)d_in[0];
    const float* y    = (const float*)d_in[1];
    const float* vals = (const float*)d_in[2];
    const float* hs   = (const float*)d_in[4];
    const float* rot  = (const float*)d_in[5];
    const float* ox   = (const float*)d_in[6];
    const float* oy   = (const float*)d_in[7];
    const int*   qmin = (const int*)  d_in[8];

    int n = in_sizes[0];
    int npix = out_size;                 // 1801
    if (npix > PADPIX) npix = PADPIX;

    hex_kernel<<<NCTA, TPB>>>(x, y, vals, hs, rot, ox, oy, qmin,
                              n / 4, npix, (float*)d_out);
    reduce_kernel<<<CTA_GROUPS * PIX_BLOCKS, 256>>>((float*)d_out, npix);
}